// round 2
// baseline (speedup 1.0000x reference)
#include <cuda_runtime.h>

// Problem constants
constexpr int Bq  = 131072;   // batch
constexpr int T   = 8;        // context window
constexpr int C   = 32;       // embed dim
constexpr int H   = 4;        // heads
constexpr int D   = 8;        // head dim (H*D == C)

constexpr int BPB = 8;        // batches per block
constexpr int THREADS = BPB * T;   // 64 threads, one per (batch, t) row

// Padded shared k/v layout: per-batch stride 296 floats (≡8 mod 32),
// per-s stride 36 floats (≡4 mod 32): the 4 batch-groups in a warp hit
// distinct banks on attention LDS.128 reads. All offsets stay 16B-aligned.
constexpr int S_STRIDE  = 36;                // floats per (s) row
constexpr int KV_STRIDE = T * S_STRIDE + 8;  // 296 floats per batch

using ull = unsigned long long;

// ---- packed f32x2 helpers (FFMA2 path: ptxas never auto-fuses this) ----
__device__ __forceinline__ ull ffma2(ull a, ull b, ull c) {
    ull d;
    asm("fma.rn.f32x2 %0, %1, %2, %3;" : "=l"(d) : "l"(a), "l"(b), "l"(c));
    return d;
}
__device__ __forceinline__ ull fmul2(ull a, ull b) {
    ull d;
    asm("mul.rn.f32x2 %0, %1, %2;" : "=l"(d) : "l"(a), "l"(b));
    return d;
}
__device__ __forceinline__ ull pack2(float lo, float hi) {
    ull r;
    asm("mov.b64 %0, {%1, %2};" : "=l"(r) : "f"(lo), "f"(hi));
    return r;
}
__device__ __forceinline__ float2 unpack2(ull v) {
    float2 r;
    asm("mov.b64 {%0, %1}, %2;" : "=f"(r.x), "=f"(r.y) : "l"(v));
    return r;
}
// horizontal sum of two packed accumulators (4 lanes)
__device__ __forceinline__ float hsum2x2(ull a, ull b) {
    float2 u = unpack2(a);
    float2 v = unpack2(b);
    return (u.x + u.y) + (v.x + v.y);
}

__global__ __launch_bounds__(THREADS)
void block_attn_ffn_kernel(const float* __restrict__ x,
                           const float* __restrict__ Wq,
                           const float* __restrict__ Wk,
                           const float* __restrict__ Wv,
                           const float* __restrict__ Wf,
                           const float* __restrict__ bf,
                           float* __restrict__ out)
{
    // Transposed weights: sW*T[j][c] = W[h][c][d] with j = h*D + d
    __shared__ __align__(16) float sWqT[C][C];
    __shared__ __align__(16) float sWkT[C][C];
    __shared__ __align__(16) float sWvT[C][C];
    __shared__ __align__(16) float sWfT[C][C];
    __shared__ float sbf[C];
    __shared__ __align__(16) float sk[BPB][KV_STRIDE];
    __shared__ __align__(16) float sv[BPB][KV_STRIDE];

    const int tid = threadIdx.x;

    // ---- Load + transpose weights into shared ----
    #pragma unroll
    for (int i = tid; i < C * C; i += THREADS) {
        int j = i >> 5;        // output index (h*D+d for qkv, out-col for f)
        int c = i & 31;        // input channel
        int h = j >> 3;
        int d = j & 7;
        int src = (h * C + c) * D + d;   // W[h][c][d]
        sWqT[j][c] = Wq[src];
        sWkT[j][c] = Wk[src];
        sWvT[j][c] = Wv[src];
        sWfT[j][c] = Wf[c * C + j];      // Wf[c_in][c_out]
    }
    if (tid < C) sbf[tid] = bf[tid];

    const int bb = tid >> 3;   // local batch 0..BPB-1
    const int t  = tid & 7;    // row within context

    const long long row = (long long)(blockIdx.x * BPB + bb) * T + t;

    // ---- Load this thread's x row as 16 packed f32x2 pairs ----
    ull xp[16];
    {
        const ulonglong2* xin = (const ulonglong2*)(x + row * C);  // 128B-aligned
        #pragma unroll
        for (int i = 0; i < 8; i++) {
            ulonglong2 p = xin[i];
            xp[2 * i + 0] = p.x;   // (x[4i],   x[4i+1])
            xp[2 * i + 1] = p.y;   // (x[4i+2], x[4i+3])
        }
    }

    __syncthreads();   // weights visible

    // ---- Phase 1: k and v rows -> shared (packed dot products) ----
    #pragma unroll 2
    for (int j = 0; j < C; j++) {
        const ulonglong2* wk = (const ulonglong2*)sWkT[j];
        const ulonglong2* wv = (const ulonglong2*)sWvT[j];
        ull ka = 0ull, kb = 0ull, va = 0ull, vb = 0ull;   // (0.f,0.f) bit pattern
        #pragma unroll
        for (int i = 0; i < 8; i++) {
            ulonglong2 wkp = wk[i];
            ulonglong2 wvp = wv[i];
            ka = ffma2(xp[2 * i + 0], wkp.x, ka);
            kb = ffma2(xp[2 * i + 1], wkp.y, kb);
            va = ffma2(xp[2 * i + 0], wvp.x, va);
            vb = ffma2(xp[2 * i + 1], wvp.y, vb);
        }
        sk[bb][t * S_STRIDE + j] = hsum2x2(ka, kb);
        sv[bb][t * S_STRIDE + j] = hsum2x2(va, vb);
    }
    __syncthreads();   // all k/v rows of this block's batches ready

    // ---- Phase 2: per-head q, causal softmax, AV (all packed) ----
    const float scale = 0.35355339059327373f;   // 1/sqrt(D)
    ull op2[16];   // attention output, packed pairs, ready for phase 3

    #pragma unroll
    for (int h = 0; h < H; h++) {
        // q row for this head, packed into 4 pairs with scale folded in
        ull qp[4];
        #pragma unroll
        for (int dp = 0; dp < 4; dp++) {   // pair of d: (2dp, 2dp+1)
            float qv[2];
            #pragma unroll
            for (int u = 0; u < 2; u++) {
                const ulonglong2* wq = (const ulonglong2*)sWqT[h * D + 2 * dp + u];
                ull a = 0ull, b = 0ull;
                #pragma unroll
                for (int i = 0; i < 8; i++) {
                    ulonglong2 w = wq[i];
                    a = ffma2(xp[2 * i + 0], w.x, a);
                    b = ffma2(xp[2 * i + 1], w.y, b);
                }
                qv[u] = hsum2x2(a, b) * scale;
            }
            qp[dp] = pack2(qv[0], qv[1]);
        }

        // scores vs all s (causal mask via select)
        float sc[T];
        #pragma unroll
        for (int s = 0; s < T; s++) {
            const ulonglong2* kp = (const ulonglong2*)&sk[bb][s * S_STRIDE + h * D];
            ulonglong2 k0 = kp[0];   // pairs (d0,d1),(d2,d3)
            ulonglong2 k1 = kp[1];   // pairs (d4,d5),(d6,d7)
            ull a = 0ull, b = 0ull;
            a = ffma2(qp[0], k0.x, a);
            b = ffma2(qp[1], k0.y, b);
            a = ffma2(qp[2], k1.x, a);
            b = ffma2(qp[3], k1.y, b);
            float dot = hsum2x2(a, b);
            sc[s] = (s <= t) ? dot : -1e30f;
        }

        // softmax
        float m = sc[0];
        #pragma unroll
        for (int s = 1; s < T; s++) m = fmaxf(m, sc[s]);
        float sum = 0.f;
        #pragma unroll
        for (int s = 0; s < T; s++) {
            sc[s] = __expf(sc[s] - m);
            sum += sc[s];
        }
        float inv = 1.0f / sum;

        // weighted sum of v, accumulated in packed pairs
        ull o0 = 0ull, o1 = 0ull, o2 = 0ull, o3 = 0ull;
        #pragma unroll
        for (int s = 0; s < T; s++) {
            const ulonglong2* vp = (const ulonglong2*)&sv[bb][s * S_STRIDE + h * D];
            ulonglong2 v0 = vp[0];
            ulonglong2 v1 = vp[1];
            ull w2 = pack2(sc[s], sc[s]);
            o0 = ffma2(w2, v0.x, o0);
            o1 = ffma2(w2, v0.y, o1);
            o2 = ffma2(w2, v1.x, o2);
            o3 = ffma2(w2, v1.y, o3);
        }
        ull inv2 = pack2(inv, inv);
        op2[h * 4 + 0] = fmul2(o0, inv2);
        op2[h * 4 + 1] = fmul2(o1, inv2);
        op2[h * 4 + 2] = fmul2(o2, inv2);
        op2[h * 4 + 3] = fmul2(o3, inv2);
    }

    // ---- Phase 3: output projection + bias + ReLU (packed) ----
    float4* op = (float4*)(out + row * C);
    #pragma unroll 2
    for (int j4 = 0; j4 < 8; j4++) {
        float r[4];
        #pragma unroll
        for (int u = 0; u < 4; u++) {
            int j = j4 * 4 + u;
            const ulonglong2* wf = (const ulonglong2*)sWfT[j];
            ull a = 0ull, b = 0ull;
            #pragma unroll
            for (int i = 0; i < 8; i++) {
                ulonglong2 w = wf[i];
                a = ffma2(op2[2 * i + 0], w.x, a);
                b = ffma2(op2[2 * i + 1], w.y, b);
            }
            r[u] = fmaxf(sbf[j] + hsum2x2(a, b), 0.f);
        }
        float4 q;
        q.x = r[0]; q.y = r[1]; q.z = r[2]; q.w = r[3];
        op[j4] = q;
    }
}

extern "C" void kernel_launch(void* const* d_in, const int* in_sizes, int n_in,
                              void* d_out, int out_size)
{
    const float* x  = (const float*)d_in[0];
    const float* Wq = (const float*)d_in[1];
    const float* Wk = (const float*)d_in[2];
    const float* Wv = (const float*)d_in[3];
    const float* Wf = (const float*)d_in[4];
    const float* bf = (const float*)d_in[5];
    float* out = (float*)d_out;

    dim3 grid(Bq / BPB);
    dim3 block(THREADS);
    block_attn_ffn_kernel<<<grid, block>>>(x, Wq, Wk, Wv, Wf, bf, out);
}

// round 12
// speedup vs baseline: 1.7589x; 1.7589x over previous
#include <cuda_runtime.h>
#include <cstdint>

// Problem constants
constexpr int Bq  = 131072;   // batch
constexpr int T   = 8;        // context window
constexpr int C   = 32;       // embed dim
constexpr int H   = 4;        // heads
constexpr int Dh  = 8;        // head dim

constexpr int ROWS_PB = 128;  // rows (b,t pairs) per block = 16 batches
constexpr int THREADS = 128;  // 4 warps
constexpr int QSTRIDE = 36;   // base float stride for sQ/sK/sV rows

// Dynamic shared layout
constexpr int WB_BYTES   = 4 * 4 * 4 * 32 * 16;         // uint4[4][4][4][32] = 32768
constexpr int QKV_FLOATS = ROWS_PB * QSTRIDE + 48;      // 4656 floats (skew + block-pad headroom)
constexpr int SMEM_TOTAL = WB_BYTES + 3 * QKV_FLOATS * 4 + 128;   // 88768 B

// Row base with per-batch-group bank skew: groups (r>>3)&3 get +0/+16/+32/+48B so the
// 4 batch-groups of a warp hit disjoint bank quarters on attention LDS.128 reads.
// The +12*(r>>5) block pad keeps row pitch >= 36 floats when the skew wraps 12->0 at
// 32-row boundaries (R8 failure: without it rows 31/32 etc. overlapped by 8 floats,
// racing across warps -> rel_err 6.7e-2). Constant within a warp -> bank math intact.
__device__ __forceinline__ int rowoff(int r) {
    return r * QSTRIDE + ((r >> 3) & 3) * 4 + (r >> 5) * 12;
}

__device__ __forceinline__ uint32_t f2tf32(float f) {
    uint32_t r;
    asm("cvt.rna.tf32.f32 %0, %1;" : "=r"(r) : "f"(f));
    return r;
}

// D += A(16x8 tf32) * B(8x8 tf32), fp32 accumulate
__device__ __forceinline__ void mma_tf32(float& d0, float& d1, float& d2, float& d3,
                                         uint32_t a0, uint32_t a1, uint32_t a2, uint32_t a3,
                                         uint32_t b0, uint32_t b1) {
    asm volatile(
        "mma.sync.aligned.m16n8k8.row.col.f32.tf32.tf32.f32 "
        "{%0,%1,%2,%3}, {%4,%5,%6,%7}, {%8,%9}, {%0,%1,%2,%3};"
        : "+f"(d0), "+f"(d1), "+f"(d2), "+f"(d3)
        : "r"(a0), "r"(a1), "r"(a2), "r"(a3), "r"(b0), "r"(b1));
}

// split fp32 -> tf32 hi + tf32 lo
__device__ __forceinline__ void split_tf32(float v, uint32_t& hi, uint32_t& lo) {
    hi = f2tf32(v);
    lo = f2tf32(v - __uint_as_float(hi));
}

__global__ __launch_bounds__(THREADS)
void block_attn_ffn_mma(const float* __restrict__ x,
                        const float* __restrict__ Wq,
                        const float* __restrict__ Wk,
                        const float* __restrict__ Wv,
                        const float* __restrict__ Wf,
                        const float* __restrict__ bf,
                        float* __restrict__ out)
{
    extern __shared__ unsigned char smem[];
    uint4* sWB = (uint4*)smem;     // [m][kc][nt][lane] = (b0h, b1h, b0l, b1l)
    float* sQ  = (float*)(smem + WB_BYTES);
    float* sK  = sQ + QKV_FLOATS;
    float* sV  = sK + QKV_FLOATS;
    float* sBf = sV + QKV_FLOATS;

    const int tid = threadIdx.x;
    const float scale = 0.35355339059327373f;   // 1/sqrt(D), folded into Wq

    // ---- One-time per block: pack weights into B-fragment layout (tf32 hi+lo) ----
    // b0 = W[kc*8+tig][nt*8+g], b1 = W[kc*8+4+tig][nt*8+g]   (W indexed [c][j])
    #pragma unroll
    for (int i = tid; i < 2048; i += THREADS) {
        int lane = i & 31, nt = (i >> 5) & 3, kc = (i >> 7) & 3, m = i >> 9;
        int tig = lane & 3, g = lane >> 2;
        int c0 = kc * 8 + tig, c1 = c0 + 4;
        int j  = nt * 8 + g;
        float w0, w1;
        if (m == 3) {
            w0 = Wf[c0 * C + j];
            w1 = Wf[c1 * C + j];
        } else {
            const float* W = (m == 0) ? Wq : (m == 1) ? Wk : Wv;
            int h = j >> 3, d = j & 7;
            w0 = W[(h * C + c0) * Dh + d];
            w1 = W[(h * C + c1) * Dh + d];
            if (m == 0) { w0 *= scale; w1 *= scale; }
        }
        uint32_t h0, l0, h1, l1;
        split_tf32(w0, h0, l0);
        split_tf32(w1, h1, l1);
        sWB[i] = make_uint4(h0, h1, l0, l1);
    }
    if (tid < C) sBf[tid] = bf[tid];

    const int lane = tid & 31, warp = tid >> 5;
    const int g = lane >> 2, tig = lane & 3;

    __syncthreads();

    // ---- Phase 1: Q,K,V projections via tf32 mma (x and W split hi/lo) ----
    #pragma unroll
    for (int t2 = 0; t2 < 2; t2++) {
        const int rl = warp * 32 + t2 * 16;                              // local row base
        const long long gr = (long long)blockIdx.x * ROWS_PB + rl;       // global row base
        uint32_t ah[4][4], al[4][4];
        #pragma unroll
        for (int kc = 0; kc < 4; kc++) {
            const float* p0 = x + (gr + g)     * C + kc * 8 + tig;
            const float* p1 = x + (gr + g + 8) * C + kc * 8 + tig;
            split_tf32(p0[0], ah[kc][0], al[kc][0]);
            split_tf32(p1[0], ah[kc][1], al[kc][1]);
            split_tf32(p0[4], ah[kc][2], al[kc][2]);
            split_tf32(p1[4], ah[kc][3], al[kc][3]);
        }
        const int ro0 = rowoff(rl + g), ro1 = rowoff(rl + g + 8);
        #pragma unroll
        for (int m = 0; m < 3; m++) {
            float* dst = (m == 0) ? sQ : (m == 1) ? sK : sV;
            #pragma unroll
            for (int nt = 0; nt < 4; nt++) {
                float d0 = 0.f, d1 = 0.f, d2 = 0.f, d3 = 0.f;
                #pragma unroll
                for (int kc = 0; kc < 4; kc++) {
                    uint4 b = sWB[((m * 4 + kc) * 4 + nt) * 32 + lane];
                    // Ah*Bh + Al*Bh + Ah*Bl  (Al*Bl ~2^-22, dropped)
                    mma_tf32(d0, d1, d2, d3, ah[kc][0], ah[kc][1], ah[kc][2], ah[kc][3], b.x, b.y);
                    mma_tf32(d0, d1, d2, d3, al[kc][0], al[kc][1], al[kc][2], al[kc][3], b.x, b.y);
                    mma_tf32(d0, d1, d2, d3, ah[kc][0], ah[kc][1], ah[kc][2], ah[kc][3], b.z, b.w);
                }
                int jc = nt * 8 + 2 * tig;
                *(float2*)&dst[ro0 + jc] = make_float2(d0, d1);
                *(float2*)&dst[ro1 + jc] = make_float2(d2, d3);
            }
        }
    }
    __syncthreads();

    // ---- Phase 2: attention, thread = row ----
    {
        const int r  = tid;
        const int rb = r & ~7;     // batch base row
        const int t  = r & 7;
        const int ro = rowoff(r);
        float o[C];

        #pragma unroll
        for (int h = 0; h < H; h++) {
            float4 q0 = *(float4*)&sQ[ro + h * 8];
            float4 q1 = *(float4*)&sQ[ro + h * 8 + 4];

            float sc[T];
            #pragma unroll
            for (int s = 0; s < T; s++) {
                const int rs = rowoff(rb + s);
                float4 k0 = *(float4*)&sK[rs + h * 8];
                float4 k1 = *(float4*)&sK[rs + h * 8 + 4];
                float a = 0.f;
                a = fmaf(q0.x, k0.x, a); a = fmaf(q0.y, k0.y, a);
                a = fmaf(q0.z, k0.z, a); a = fmaf(q0.w, k0.w, a);
                a = fmaf(q1.x, k1.x, a); a = fmaf(q1.y, k1.y, a);
                a = fmaf(q1.z, k1.z, a); a = fmaf(q1.w, k1.w, a);
                sc[s] = (s <= t) ? a : -1e30f;
            }
            float mx = sc[0];
            #pragma unroll
            for (int s = 1; s < T; s++) mx = fmaxf(mx, sc[s]);
            float sum = 0.f;
            #pragma unroll
            for (int s = 0; s < T; s++) { sc[s] = __expf(sc[s] - mx); sum += sc[s]; }
            float inv = 1.0f / sum;

            float acc[Dh];
            #pragma unroll
            for (int d = 0; d < Dh; d++) acc[d] = 0.f;
            #pragma unroll
            for (int s = 0; s < T; s++) {
                const int rs = rowoff(rb + s);
                float4 v0 = *(float4*)&sV[rs + h * 8];
                float4 v1 = *(float4*)&sV[rs + h * 8 + 4];
                float w = sc[s];
                acc[0] = fmaf(w, v0.x, acc[0]); acc[1] = fmaf(w, v0.y, acc[1]);
                acc[2] = fmaf(w, v0.z, acc[2]); acc[3] = fmaf(w, v0.w, acc[3]);
                acc[4] = fmaf(w, v1.x, acc[4]); acc[5] = fmaf(w, v1.y, acc[5]);
                acc[6] = fmaf(w, v1.z, acc[6]); acc[7] = fmaf(w, v1.w, acc[7]);
            }
            #pragma unroll
            for (int d = 0; d < Dh; d++) o[h * Dh + d] = acc[d] * inv;
        }

        // write o into sQ row r (thread-private row: no hazard before sync)
        #pragma unroll
        for (int i = 0; i < 8; i++)
            *(float4*)&sQ[ro + i * 4] =
                make_float4(o[4 * i], o[4 * i + 1], o[4 * i + 2], o[4 * i + 3]);
    }
    __syncthreads();

    // ---- Phase 3: FFN (o @ Wf + bf, ReLU) via tf32 mma (o and Wf split hi/lo) ----
    #pragma unroll
    for (int t2 = 0; t2 < 2; t2++) {
        const int rl = warp * 32 + t2 * 16;
        const long long gr = (long long)blockIdx.x * ROWS_PB + rl;
        const int ro0 = rowoff(rl + g), ro1 = rowoff(rl + g + 8);
        uint32_t ah[4][4], al[4][4];
        #pragma unroll
        for (int kc = 0; kc < 4; kc++) {
            float v0 = sQ[ro0 + kc * 8 + tig];
            float v1 = sQ[ro1 + kc * 8 + tig];
            float v2 = sQ[ro0 + kc * 8 + tig + 4];
            float v3 = sQ[ro1 + kc * 8 + tig + 4];
            split_tf32(v0, ah[kc][0], al[kc][0]);
            split_tf32(v1, ah[kc][1], al[kc][1]);
            split_tf32(v2, ah[kc][2], al[kc][2]);
            split_tf32(v3, ah[kc][3], al[kc][3]);
        }
        #pragma unroll
        for (int nt = 0; nt < 4; nt++) {
            float d0 = 0.f, d1 = 0.f, d2 = 0.f, d3 = 0.f;
            #pragma unroll
            for (int kc = 0; kc < 4; kc++) {
                uint4 b = sWB[((3 * 4 + kc) * 4 + nt) * 32 + lane];
                mma_tf32(d0, d1, d2, d3, ah[kc][0], ah[kc][1], ah[kc][2], ah[kc][3], b.x, b.y);
                mma_tf32(d0, d1, d2, d3, al[kc][0], al[kc][1], al[kc][2], al[kc][3], b.x, b.y);
                mma_tf32(d0, d1, d2, d3, ah[kc][0], ah[kc][1], ah[kc][2], ah[kc][3], b.z, b.w);
            }
            int jc = nt * 8 + 2 * tig;
            float b0v = sBf[jc], b1v = sBf[jc + 1];
            d0 = fmaxf(d0 + b0v, 0.f);
            d1 = fmaxf(d1 + b1v, 0.f);
            d2 = fmaxf(d2 + b0v, 0.f);
            d3 = fmaxf(d3 + b1v, 0.f);
            *(float2*)&out[(gr + g)     * C + jc] = make_float2(d0, d1);
            *(float2*)&out[(gr + g + 8) * C + jc] = make_float2(d2, d3);
        }
    }
}

extern "C" void kernel_launch(void* const* d_in, const int* in_sizes, int n_in,
                              void* d_out, int out_size)
{
    const float* x  = (const float*)d_in[0];
    const float* Wq = (const float*)d_in[1];
    const float* Wk = (const float*)d_in[2];
    const float* Wv = (const float*)d_in[3];
    const float* Wf = (const float*)d_in[4];
    const float* bf = (const float*)d_in[5];
    float* out = (float*)d_out;

    cudaFuncSetAttribute(block_attn_ffn_mma,
                         cudaFuncAttributeMaxDynamicSharedMemorySize, SMEM_TOTAL);
    dim3 grid((Bq * T) / ROWS_PB);   // 8192
    dim3 block(THREADS);
    block_attn_ffn_mma<<<grid, block, SMEM_TOTAL>>>(x, Wq, Wk, Wv, Wf, bf, out);
}

// round 17
// speedup vs baseline: 1.8677x; 1.0619x over previous
#include <cuda_runtime.h>
#include <cstdint>

// Problem constants
constexpr int Bq  = 131072;   // batch
constexpr int T   = 8;        // context window
constexpr int C   = 32;       // embed dim
constexpr int H   = 4;        // heads
constexpr int Dh  = 8;        // head dim

constexpr int ROWS_PB = 128;  // rows (b,t pairs) per block = 16 batches
constexpr int THREADS = 256;  // 8 warps: one 16-row mma tile per warp
constexpr int QSTRIDE = 36;   // base float stride for sQ/sK/sV rows

// Dynamic shared layout
constexpr int WB_BYTES   = 4 * 4 * 4 * 32 * 16;         // uint4[4][4][4][32] = 32768
constexpr int QKV_FLOATS = ROWS_PB * QSTRIDE + 48;      // 4656 floats (skew + block-pad headroom)
constexpr int SMEM_TOTAL = WB_BYTES + 3 * QKV_FLOATS * 4 + 128;   // 88768 B

// Row base with per-batch-group bank skew: groups (r>>3)&3 get +0/+16/+32/+48B so the
// 4 batch-groups of a warp hit disjoint bank quarters on attention LDS.128 reads.
// The +12*(r>>5) block pad keeps row pitch >= 36 floats when the skew wraps 12->0 at
// 32-row boundaries (R8 failure: without it rows 31/32 etc. overlapped by 8 floats,
// racing across warps -> rel_err 6.7e-2). Constant within a warp -> bank math intact.
__device__ __forceinline__ int rowoff(int r) {
    return r * QSTRIDE + ((r >> 3) & 3) * 4 + (r >> 5) * 12;
}

__device__ __forceinline__ uint32_t f2tf32(float f) {
    uint32_t r;
    asm("cvt.rna.tf32.f32 %0, %1;" : "=r"(r) : "f"(f));
    return r;
}

// D += A(16x8 tf32) * B(8x8 tf32), fp32 accumulate
__device__ __forceinline__ void mma_tf32(float& d0, float& d1, float& d2, float& d3,
                                         uint32_t a0, uint32_t a1, uint32_t a2, uint32_t a3,
                                         uint32_t b0, uint32_t b1) {
    asm volatile(
        "mma.sync.aligned.m16n8k8.row.col.f32.tf32.tf32.f32 "
        "{%0,%1,%2,%3}, {%4,%5,%6,%7}, {%8,%9}, {%0,%1,%2,%3};"
        : "+f"(d0), "+f"(d1), "+f"(d2), "+f"(d3)
        : "r"(a0), "r"(a1), "r"(a2), "r"(a3), "r"(b0), "r"(b1));
}

// split fp32 -> tf32 hi + tf32 lo
__device__ __forceinline__ void split_tf32(float v, uint32_t& hi, uint32_t& lo) {
    hi = f2tf32(v);
    lo = f2tf32(v - __uint_as_float(hi));
}

__global__ __launch_bounds__(THREADS)
void block_attn_ffn_mma(const float* __restrict__ x,
                        const float* __restrict__ Wq,
                        const float* __restrict__ Wk,
                        const float* __restrict__ Wv,
                        const float* __restrict__ Wf,
                        const float* __restrict__ bf,
                        float* __restrict__ out)
{
    extern __shared__ unsigned char smem[];
    uint4* sWB = (uint4*)smem;     // [m][kc][nt][lane] = (b0h, b1h, b0l, b1l)
    float* sQ  = (float*)(smem + WB_BYTES);
    float* sK  = sQ + QKV_FLOATS;
    float* sV  = sK + QKV_FLOATS;
    float* sBf = sV + QKV_FLOATS;

    const int tid = threadIdx.x;
    const float scale = 0.35355339059327373f;   // 1/sqrt(D), folded into Wq

    // ---- One-time per block: pack weights into B-fragment layout (tf32 hi+lo) ----
    // b0 = W[kc*8+tig][nt*8+g], b1 = W[kc*8+4+tig][nt*8+g]   (W indexed [c][j])
    #pragma unroll
    for (int i = tid; i < 2048; i += THREADS) {
        int lane = i & 31, nt = (i >> 5) & 3, kc = (i >> 7) & 3, m = i >> 9;
        int tig = lane & 3, g = lane >> 2;
        int c0 = kc * 8 + tig, c1 = c0 + 4;
        int j  = nt * 8 + g;
        float w0, w1;
        if (m == 3) {
            w0 = Wf[c0 * C + j];
            w1 = Wf[c1 * C + j];
        } else {
            const float* W = (m == 0) ? Wq : (m == 1) ? Wk : Wv;
            int h = j >> 3, d = j & 7;
            w0 = W[(h * C + c0) * Dh + d];
            w1 = W[(h * C + c1) * Dh + d];
            if (m == 0) { w0 *= scale; w1 *= scale; }
        }
        uint32_t h0, l0, h1, l1;
        split_tf32(w0, h0, l0);
        split_tf32(w1, h1, l1);
        sWB[i] = make_uint4(h0, h1, l0, l1);
    }
    if (tid < C) sBf[tid] = bf[tid];

    const int lane = tid & 31, warp = tid >> 5;
    const int g = lane >> 2, tig = lane & 3;

    __syncthreads();

    // ---- Phase 1: Q,K,V projections via tf32 mma (x and W split hi/lo) ----
    // 8 warps, one 16-row tile each.
    {
        const int rl = warp * 16;                                        // local row base
        const long long gr = (long long)blockIdx.x * ROWS_PB + rl;       // global row base
        uint32_t ah[4][4], al[4][4];
        #pragma unroll
        for (int kc = 0; kc < 4; kc++) {
            const float* p0 = x + (gr + g)     * C + kc * 8 + tig;
            const float* p1 = x + (gr + g + 8) * C + kc * 8 + tig;
            split_tf32(p0[0], ah[kc][0], al[kc][0]);
            split_tf32(p1[0], ah[kc][1], al[kc][1]);
            split_tf32(p0[4], ah[kc][2], al[kc][2]);
            split_tf32(p1[4], ah[kc][3], al[kc][3]);
        }
        const int ro0 = rowoff(rl + g), ro1 = rowoff(rl + g + 8);
        #pragma unroll
        for (int m = 0; m < 3; m++) {
            float* dst = (m == 0) ? sQ : (m == 1) ? sK : sV;
            #pragma unroll
            for (int nt = 0; nt < 4; nt++) {
                float d0 = 0.f, d1 = 0.f, d2 = 0.f, d3 = 0.f;
                #pragma unroll
                for (int kc = 0; kc < 4; kc++) {
                    uint4 b = sWB[((m * 4 + kc) * 4 + nt) * 32 + lane];
                    // Ah*Bh + Al*Bh + Ah*Bl  (Al*Bl ~2^-22, dropped)
                    mma_tf32(d0, d1, d2, d3, ah[kc][0], ah[kc][1], ah[kc][2], ah[kc][3], b.x, b.y);
                    mma_tf32(d0, d1, d2, d3, al[kc][0], al[kc][1], al[kc][2], al[kc][3], b.x, b.y);
                    mma_tf32(d0, d1, d2, d3, ah[kc][0], ah[kc][1], ah[kc][2], ah[kc][3], b.z, b.w);
                }
                int jc = nt * 8 + 2 * tig;
                *(float2*)&dst[ro0 + jc] = make_float2(d0, d1);
                *(float2*)&dst[ro1 + jc] = make_float2(d2, d3);
            }
        }
    }
    __syncthreads();

    // ---- Phase 2: attention; 256 threads = (row, head-pair) ----
    // Thread handles row (tid&127), heads h0=2*(tid>>7)..h0+1; the two threads
    // per row write disjoint 16-float halves of o into sQ -> no hazard.
    {
        const int r  = tid & 127;
        const int h0 = (tid >> 7) * 2;
        const int rb = r & ~7;     // batch base row
        const int t  = r & 7;
        const int ro = rowoff(r);
        float o[16];

        #pragma unroll
        for (int hh = 0; hh < 2; hh++) {
            const int h = h0 + hh;
            float4 q0 = *(float4*)&sQ[ro + h * 8];
            float4 q1 = *(float4*)&sQ[ro + h * 8 + 4];

            float sc[T];
            #pragma unroll
            for (int s = 0; s < T; s++) {
                const int rs = rowoff(rb + s);
                float4 k0 = *(float4*)&sK[rs + h * 8];
                float4 k1 = *(float4*)&sK[rs + h * 8 + 4];
                float a = 0.f;
                a = fmaf(q0.x, k0.x, a); a = fmaf(q0.y, k0.y, a);
                a = fmaf(q0.z, k0.z, a); a = fmaf(q0.w, k0.w, a);
                a = fmaf(q1.x, k1.x, a); a = fmaf(q1.y, k1.y, a);
                a = fmaf(q1.z, k1.z, a); a = fmaf(q1.w, k1.w, a);
                sc[s] = (s <= t) ? a : -1e30f;
            }
            float mx = sc[0];
            #pragma unroll
            for (int s = 1; s < T; s++) mx = fmaxf(mx, sc[s]);
            float sum = 0.f;
            #pragma unroll
            for (int s = 0; s < T; s++) { sc[s] = __expf(sc[s] - mx); sum += sc[s]; }
            float inv = 1.0f / sum;

            float acc[Dh];
            #pragma unroll
            for (int d = 0; d < Dh; d++) acc[d] = 0.f;
            #pragma unroll
            for (int s = 0; s < T; s++) {
                const int rs = rowoff(rb + s);
                float4 v0 = *(float4*)&sV[rs + h * 8];
                float4 v1 = *(float4*)&sV[rs + h * 8 + 4];
                float w = sc[s];
                acc[0] = fmaf(w, v0.x, acc[0]); acc[1] = fmaf(w, v0.y, acc[1]);
                acc[2] = fmaf(w, v0.z, acc[2]); acc[3] = fmaf(w, v0.w, acc[3]);
                acc[4] = fmaf(w, v1.x, acc[4]); acc[5] = fmaf(w, v1.y, acc[5]);
                acc[6] = fmaf(w, v1.z, acc[6]); acc[7] = fmaf(w, v1.w, acc[7]);
            }
            #pragma unroll
            for (int d = 0; d < Dh; d++) o[hh * Dh + d] = acc[d] * inv;
        }

        // write this thread's 2-head half of o into sQ row r
        #pragma unroll
        for (int i = 0; i < 4; i++)
            *(float4*)&sQ[ro + h0 * 8 + i * 4] =
                make_float4(o[4 * i], o[4 * i + 1], o[4 * i + 2], o[4 * i + 3]);
    }
    __syncthreads();

    // ---- Phase 3: FFN (o @ Wf + bf, ReLU) via tf32 mma (o and Wf split hi/lo) ----
    {
        const int rl = warp * 16;
        const long long gr = (long long)blockIdx.x * ROWS_PB + rl;
        const int ro0 = rowoff(rl + g), ro1 = rowoff(rl + g + 8);
        uint32_t ah[4][4], al[4][4];
        #pragma unroll
        for (int kc = 0; kc < 4; kc++) {
            float v0 = sQ[ro0 + kc * 8 + tig];
            float v1 = sQ[ro1 + kc * 8 + tig];
            float v2 = sQ[ro0 + kc * 8 + tig + 4];
            float v3 = sQ[ro1 + kc * 8 + tig + 4];
            split_tf32(v0, ah[kc][0], al[kc][0]);
            split_tf32(v1, ah[kc][1], al[kc][1]);
            split_tf32(v2, ah[kc][2], al[kc][2]);
            split_tf32(v3, ah[kc][3], al[kc][3]);
        }
        #pragma unroll
        for (int nt = 0; nt < 4; nt++) {
            float d0 = 0.f, d1 = 0.f, d2 = 0.f, d3 = 0.f;
            #pragma unroll
            for (int kc = 0; kc < 4; kc++) {
                uint4 b = sWB[((3 * 4 + kc) * 4 + nt) * 32 + lane];
                mma_tf32(d0, d1, d2, d3, ah[kc][0], ah[kc][1], ah[kc][2], ah[kc][3], b.x, b.y);
                mma_tf32(d0, d1, d2, d3, al[kc][0], al[kc][1], al[kc][2], al[kc][3], b.x, b.y);
                mma_tf32(d0, d1, d2, d3, ah[kc][0], ah[kc][1], ah[kc][2], ah[kc][3], b.z, b.w);
            }
            int jc = nt * 8 + 2 * tig;
            float b0v = sBf[jc], b1v = sBf[jc + 1];
            d0 = fmaxf(d0 + b0v, 0.f);
            d1 = fmaxf(d1 + b1v, 0.f);
            d2 = fmaxf(d2 + b0v, 0.f);
            d3 = fmaxf(d3 + b1v, 0.f);
            *(float2*)&out[(gr + g)     * C + jc] = make_float2(d0, d1);
            *(float2*)&out[(gr + g + 8) * C + jc] = make_float2(d2, d3);
        }
    }
}

extern "C" void kernel_launch(void* const* d_in, const int* in_sizes, int n_in,
                              void* d_out, int out_size)
{
    const float* x  = (const float*)d_in[0];
    const float* Wq = (const float*)d_in[1];
    const float* Wk = (const float*)d_in[2];
    const float* Wv = (const float*)d_in[3];
    const float* Wf = (const float*)d_in[4];
    const float* bf = (const float*)d_in[5];
    float* out = (float*)d_out;

    cudaFuncSetAttribute(block_attn_ffn_mma,
                         cudaFuncAttributeMaxDynamicSharedMemorySize, SMEM_TOTAL);
    dim3 grid((Bq * T) / ROWS_PB);   // 8192
    dim3 block(THREADS);
    block_attn_ffn_mma<<<grid, block, SMEM_TOTAL>>>(x, Wq, Wk, Wv, Wf, bf, out);
}